// round 5
// baseline (speedup 1.0000x reference)
#include <cuda_runtime.h>
#include <stdint.h>

#define CAP   6144     // stage-1 candidates (raw x, x > sample_max - 2)
#define CAP2  2048     // stage-2 candidates (Y > -1, true support superset)
#define MAX_ROWS 16384

__device__ float    g_row_loss[MAX_ROWS];
__device__ unsigned g_done = 0;

__device__ __forceinline__ float warpMax(float v) {
    #pragma unroll
    for (int o = 16; o; o >>= 1) v = fmaxf(v, __shfl_xor_sync(0xffffffffu, v, o));
    return v;
}
__device__ __forceinline__ float warpSum(float v) {
    #pragma unroll
    for (int o = 16; o; o >>= 1) v += __shfl_xor_sync(0xffffffffu, v, o);
    return v;
}

// Warp-aggregated compaction: one shared atomic per warp instead of per lane.
__device__ __forceinline__ void push(bool take, float v, int* cnt,
                                     float* buf, int cap, int lane) {
    unsigned m = __ballot_sync(0xffffffffu, take);
    if (m) {
        int leader = __ffs(m) - 1;
        int base = 0;
        if (lane == leader) base = atomicAdd(cnt, __popc(m));
        base = __shfl_sync(0xffffffffu, base, leader);
        if (take) {
            int id = base + __popc(m & ((1u << lane) - 1u));
            if (id < cap) buf[id] = v;
        }
    }
}

__device__ __forceinline__ void proc4(float4 v, float thr, float& vmax,
                                      int* cnt, float* buf, int lane) {
    vmax = fmaxf(fmaxf(v.x, v.y), fmaxf(fmaxf(v.z, v.w), vmax));
    push(v.x > thr, v.x, cnt, buf, CAP, lane);
    push(v.y > thr, v.y, cnt, buf, CAP, lane);
    push(v.z > thr, v.z, cnt, buf, CAP, lane);
    push(v.w > thr, v.w, cnt, buf, CAP, lane);
}

__global__ __launch_bounds__(512, 3)
void entmax15_loss_kernel(const float* __restrict__ input,
                          const void* __restrict__ target,
                          int n, int d, float* __restrict__ out) {
    __shared__ float cand[CAP];
    __shared__ float candY[CAP2];
    __shared__ float shA[16], shB[16], shC[16];
    __shared__ float s_red0, s_red1;
    __shared__ int   s_count, s_count2, s_tg32, s_last;
    __shared__ float s_tau, s_xt;

    const int tid  = threadIdx.x;
    const int lane = tid & 31;
    const int wid  = tid >> 5;
    const int bd   = blockDim.x;
    const int nw   = bd >> 5;

    const float* in_row = input + (size_t)blockIdx.x * (size_t)d;
    const bool al = ((((uintptr_t)in_row) & 15) == 0) && ((d & 3) == 0);

    if (tid == 0) { s_count = 0; s_count2 = 0; }

    // ---- dtype probe (warp 0): int32 buffer read as int64 leaves [0,d) ----
    if (wid == 0) {
        int lim = n >> 1; if (lim > 32) lim = 32;
        bool bad = false;
        if (lane < lim) {
            long long v = ((const long long*)target)[lane];
            bad = (v < 0 || v >= (long long)d);
        }
        unsigned mk = __ballot_sync(0xffffffffu, bad);
        if (lane == 0) s_tg32 = (mk != 0);
    }

    // ---- Sample max over first min(d,4096) elements ----
    const int slen = (d < 4096) ? d : 4096;
    float smax = -INFINITY;
    if (al) {
        const float4* in4 = (const float4*)in_row;
        const int s4 = slen >> 2;
        for (int i = tid; i < s4; i += bd) {
            float4 v = in4[i];
            smax = fmaxf(fmaxf(v.x, v.y), fmaxf(fmaxf(v.z, v.w), smax));
        }
    } else {
        for (int i = tid; i < slen; i += bd) smax = fmaxf(smax, in_row[i]);
    }
    smax = warpMax(smax);
    if (lane == 0) shA[wid] = smax;
    __syncthreads();
    if (tid < 32) {
        float m = (tid < nw) ? shA[tid] : -INFINITY;
        m = warpMax(m);
        if (tid == 0) s_red0 = m;
    }
    __syncthreads();
    const float thr = s_red0 - 2.0f;   // collect x > thr (superset of support)

    if (tid == 0) {
        long long tg = s_tg32 ? (long long)(((const int*)target)[blockIdx.x])
                              : ((const long long*)target)[blockIdx.x];
        if (tg < 0) tg = 0;
        if (tg >= d) tg = d - 1;
        s_xt = in_row[tg];
    }

    // ---- SINGLE full-row pass: max + collect, MLP=4 prefetch ----
    float vmax = -INFINITY;
    if (al) {
        const float4* in4 = (const float4*)in_row;
        const int d4 = d >> 2;
        int i = tid;
        for (; i + 3 * bd < d4; i += 4 * bd) {
            // 4 independent loads issued before any compaction logic
            float4 a = in4[i];
            float4 b = in4[i + bd];
            float4 c = in4[i + 2 * bd];
            float4 e = in4[i + 3 * bd];
            proc4(a, thr, vmax, &s_count, cand, lane);
            proc4(b, thr, vmax, &s_count, cand, lane);
            proc4(c, thr, vmax, &s_count, cand, lane);
            proc4(e, thr, vmax, &s_count, cand, lane);
        }
        for (; i < d4; i += bd) {
            float4 a = in4[i];
            proc4(a, thr, vmax, &s_count, cand, lane);
        }
    } else {
        for (int i = tid; i < d; i += bd) {
            float x = in_row[i];
            vmax = fmaxf(vmax, x);
            push(x > thr, x, &s_count, cand, CAP, lane);
        }
    }
    vmax = warpMax(vmax);
    if (lane == 0) shA[wid] = vmax;
    __syncthreads();
    if (tid < 32) {
        float m = (tid < nw) ? shA[tid] : -INFINITY;
        m = warpMax(m);
        if (tid == 0) s_red0 = m;
    }
    __syncthreads();
    const float M = 0.5f * s_red0;          // max of X = input/2
    const int  count = s_count;
    const bool fit = (count <= CAP);        // block-uniform

    // ---- Stage-2 compaction: keep Y = x/2 - M > -1 ----
    if (fit) {
        for (int i = tid; i < ((count + bd - 1) / bd) * bd; i += bd) {
            bool  in = (i < count);
            float y  = in ? fmaf(0.5f, cand[i], -M) : -2.0f;
            push(in && (y > -1.0f), y, &s_count2, candY, CAP2, lane);
        }
    }
    __syncthreads();
    const int  count2 = s_count2;
    const bool fit2 = fit && (count2 <= CAP2);

    // ---- Newton on f(tau) = sum max(Y-tau,0)^2 = 1, root in [-1,0) ----
    float tau;
    if (fit) {
        const float* buf = fit2 ? candY : cand;
        const int    len = fit2 ? count2 : count;
        const bool   isY = fit2;
        if (wid == 0) {
            float tl = -1.0f;
            #pragma unroll 1
            for (int it = 0; it < 20; ++it) {
                float s1 = 0.f, s2 = 0.f;
                for (int i = lane; i < len; i += 32) {
                    float y = isY ? buf[i] : fmaf(0.5f, buf[i], -M);
                    float t = y - tl;
                    if (t > 0.f) { s1 += t; s2 = fmaf(t, t, s2); }
                }
                s1 = warpSum(s1); s2 = warpSum(s2);
                float corr = (s2 - 1.0f) / (2.0f * fmaxf(s1, 1e-30f));
                tl += corr;
                if (fabsf(corr) < 1e-8f) break;
            }
            if (lane == 0) s_tau = tl;
        }
        __syncthreads();
        tau = s_tau;
    } else {
        // Rare fallback: block-wide Newton over the full row (L2 reads).
        tau = -1.0f;
        for (int it = 0; it < 24; ++it) {
            float s1 = 0.f, s2 = 0.f;
            for (int i = tid; i < d; i += bd) {
                float t = fmaf(0.5f, in_row[i], -M) - tau;
                if (t > 0.f) { s1 += t; s2 = fmaf(t, t, s2); }
            }
            s1 = warpSum(s1); s2 = warpSum(s2);
            if (lane == 0) { shA[wid] = s1; shB[wid] = s2; }
            __syncthreads();
            if (tid < 32) {
                float a = (tid < nw) ? shA[tid] : 0.f;
                float b = (tid < nw) ? shB[tid] : 0.f;
                a = warpSum(a); b = warpSum(b);
                if (tid == 0) { s_red0 = a; s_red1 = b; }
            }
            __syncthreads();
            tau += (s_red1 - 1.0f) / (2.0f * fmaxf(s_red0, 1e-30f));
            __syncthreads();
        }
    }

    // ---- Epilogue: loss = (1 - sum t^3)*4/3 + 2*sum t^2*Y + 2*M*sum t^2 - x[tg] ----
    float t3 = 0.f, py = 0.f, p2 = 0.f;
    if (fit) {
        const float* buf = fit2 ? candY : cand;
        const int    len = fit2 ? count2 : count;
        const bool   isY = fit2;
        for (int i = tid; i < len; i += bd) {
            float y = isY ? buf[i] : fmaf(0.5f, buf[i], -M);
            float t = y - tau;
            if (t > 0.f) { float p = t * t; t3 = fmaf(p, t, t3); py = fmaf(p, y, py); p2 += p; }
        }
    } else {
        for (int i = tid; i < d; i += bd) {
            float y = fmaf(0.5f, in_row[i], -M);
            float t = y - tau;
            if (t > 0.f) { float p = t * t; t3 = fmaf(p, t, t3); py = fmaf(p, y, py); p2 += p; }
        }
    }
    t3 = warpSum(t3); py = warpSum(py); p2 = warpSum(p2);
    if (lane == 0) { shA[wid] = t3; shB[wid] = py; shC[wid] = p2; }
    __syncthreads();
    if (tid < 32) {
        float a = (tid < nw) ? shA[tid] : 0.f;
        float b = (tid < nw) ? shB[tid] : 0.f;
        float c = (tid < nw) ? shC[tid] : 0.f;
        a = warpSum(a); b = warpSum(b); c = warpSum(c);
        if (tid == 0) {
            float omega = (1.0f - a) * (4.0f / 3.0f);
            g_row_loss[blockIdx.x] = omega + 2.0f * b + 2.0f * M * c - s_xt;
        }
    }
    __syncthreads();

    // ---- Deterministic in-kernel mean: last block to finish reduces ----
    if (tid == 0) {
        __threadfence();
        unsigned prev = atomicAdd(&g_done, 1u);
        s_last = (prev == (unsigned)(n - 1));
    }
    __syncthreads();
    if (s_last) {
        float a = 0.f;
        for (int i = tid; i < n; i += bd) a += g_row_loss[i];  // fixed order
        a = warpSum(a);
        if (lane == 0) shA[wid] = a;
        __syncthreads();
        if (tid < 32) {
            float v = (tid < nw) ? shA[tid] : 0.f;
            v = warpSum(v);
            if (tid == 0) { out[0] = v / (float)n; g_done = 0u; }
        }
    }
}

extern "C" void kernel_launch(void* const* d_in, const int* in_sizes, int n_in,
                              void* d_out, int out_size) {
    const int i_in = (in_sizes[0] >= in_sizes[1]) ? 0 : 1;
    const int i_tg = 1 - i_in;
    const float* input  = (const float*)d_in[i_in];
    const void*  target = d_in[i_tg];
    const int n = in_sizes[i_tg];
    const int d = in_sizes[i_in] / n;

    entmax15_loss_kernel<<<n, 512>>>(input, target, n, d, (float*)d_out);
}

// round 6
// speedup vs baseline: 1.1655x; 1.1655x over previous
#include <cuda_runtime.h>
#include <stdint.h>

#define CAP   6144     // stage-1 candidates (raw x, x > sample_max - 2)
#define CAP2  2048     // stage-2 candidates (Y > -1)
#define MAX_ROWS 16384

__device__ float    g_row_loss[MAX_ROWS];
__device__ unsigned g_done = 0;

__device__ __forceinline__ float warpMax(float v) {
    #pragma unroll
    for (int o = 16; o; o >>= 1) v = fmaxf(v, __shfl_xor_sync(0xffffffffu, v, o));
    return v;
}
__device__ __forceinline__ float warpSum(float v) {
    #pragma unroll
    for (int o = 16; o; o >>= 1) v += __shfl_xor_sync(0xffffffffu, v, o);
    return v;
}

__global__ __launch_bounds__(512, 4)
void entmax15_loss_kernel(const float* __restrict__ input,
                          const void* __restrict__ target,
                          int n, int d, float* __restrict__ out) {
    __shared__ float cand[CAP];
    __shared__ float candY[CAP2];
    __shared__ float shA[16], shB[16], shC[16];
    __shared__ float s_red0, s_red1;
    __shared__ int   s_count, s_count2, s_tg32, s_last;
    __shared__ float s_tau, s_xt;

    const int tid  = threadIdx.x;
    const int lane = tid & 31;
    const int wid  = tid >> 5;
    const int bd   = blockDim.x;
    const int nw   = bd >> 5;

    const float* in_row = input + (size_t)blockIdx.x * (size_t)d;
    const bool al = ((((uintptr_t)in_row) & 15) == 0) && ((d & 3) == 0);

    if (tid == 0) { s_count = 0; s_count2 = 0; }

    // ---- dtype probe (warp 0): int32 buffer read as int64 leaves [0,d) ----
    if (wid == 0) {
        int lim = n >> 1; if (lim > 32) lim = 32;
        bool bad = false;
        if (lane < lim) {
            long long v = ((const long long*)target)[lane];
            bad = (v < 0 || v >= (long long)d);
        }
        unsigned mk = __ballot_sync(0xffffffffu, bad);
        if (lane == 0) s_tg32 = (mk != 0);
    }

    // ---- Sample max over first min(d,4096) elements ----
    const int slen = (d < 4096) ? d : 4096;
    float smax = -INFINITY;
    if (al) {
        const float4* in4 = (const float4*)in_row;
        const int s4 = slen >> 2;
        for (int i = tid; i < s4; i += bd) {
            float4 v = in4[i];
            smax = fmaxf(fmaxf(v.x, v.y), fmaxf(fmaxf(v.z, v.w), smax));
        }
    } else {
        for (int i = tid; i < slen; i += bd) smax = fmaxf(smax, in_row[i]);
    }
    smax = warpMax(smax);
    if (lane == 0) shA[wid] = smax;
    __syncthreads();
    if (tid < 32) {
        float m = (tid < nw) ? shA[tid] : -INFINITY;
        m = warpMax(m);
        if (tid == 0) s_red0 = m;
    }
    __syncthreads();
    // True max M_x >= smax, and support is x > 2*M - 2 >= smax - 2.
    const float thr = s_red0 - 2.0f;

    if (tid == 0) {
        long long tg = s_tg32 ? (long long)(((const int*)target)[blockIdx.x])
                              : ((const long long*)target)[blockIdx.x];
        if (tg < 0) tg = 0;
        if (tg >= d) tg = d - 1;
        s_xt = in_row[tg];
    }

    // ---- SINGLE full-row pass: 1 compare + 1 ballot per float4 ----
    float vmax = -INFINITY;
    if (al) {
        const float4* in4 = (const float4*)in_row;
        const int d4 = d >> 2;
        const int iters = (d4 + bd - 1) / bd;        // warp-uniform trip count
        for (int k = 0; k < iters; ++k) {
            int i = tid + k * bd;
            bool valid = (i < d4);
            float4 v;
            if (valid) v = in4[i];
            else       v = make_float4(-INFINITY, -INFINITY, -INFINITY, -INFINITY);
            float gm = fmaxf(fmaxf(v.x, v.y), fmaxf(v.z, v.w));
            vmax = fmaxf(vmax, gm);
            unsigned any = __ballot_sync(0xffffffffu, gm > thr);
            if (any) {  // warp-collective slow path, once per visit
                unsigned mx = __ballot_sync(0xffffffffu, v.x > thr);
                unsigned my = __ballot_sync(0xffffffffu, v.y > thr);
                unsigned mz = __ballot_sync(0xffffffffu, v.z > thr);
                unsigned mw = __ballot_sync(0xffffffffu, v.w > thr);
                int cx = __popc(mx), cy = __popc(my), cz = __popc(mz);
                int total = cx + cy + cz + __popc(mw);
                int base = 0;
                if (lane == 0) base = atomicAdd(&s_count, total);
                base = __shfl_sync(0xffffffffu, base, 0);
                unsigned lt = (1u << lane) - 1u;
                if (v.x > thr) { int id = base + __popc(mx & lt);                 if (id < CAP) cand[id] = v.x; }
                if (v.y > thr) { int id = base + cx + __popc(my & lt);            if (id < CAP) cand[id] = v.y; }
                if (v.z > thr) { int id = base + cx + cy + __popc(mz & lt);       if (id < CAP) cand[id] = v.z; }
                if (v.w > thr) { int id = base + cx + cy + cz + __popc(mw & lt);  if (id < CAP) cand[id] = v.w; }
            }
        }
    } else {
        const int iters = (d + bd - 1) / bd;
        for (int k = 0; k < iters; ++k) {
            int i = tid + k * bd;
            float x = (i < d) ? in_row[i] : -INFINITY;
            vmax = fmaxf(vmax, x);
            unsigned m = __ballot_sync(0xffffffffu, x > thr);
            if (m) {
                int base = 0;
                if (lane == 0) base = atomicAdd(&s_count, __popc(m));
                base = __shfl_sync(0xffffffffu, base, 0);
                if (x > thr) {
                    int id = base + __popc(m & ((1u << lane) - 1u));
                    if (id < CAP) cand[id] = x;
                }
            }
        }
    }
    vmax = warpMax(vmax);
    if (lane == 0) shA[wid] = vmax;
    __syncthreads();
    if (tid < 32) {
        float m = (tid < nw) ? shA[tid] : -INFINITY;
        m = warpMax(m);
        if (tid == 0) s_red0 = m;
    }
    __syncthreads();
    const float M = 0.5f * s_red0;          // max of X = input/2
    const int  count = s_count;
    const bool fit = (count <= CAP);        // block-uniform

    // ---- Stage-2 compaction: keep Y = x/2 - M > -1 ----
    if (fit) {
        const int iters = (count + bd - 1) / bd;
        for (int k = 0; k < iters; ++k) {
            int i = tid + k * bd;
            float y = (i < count) ? fmaf(0.5f, cand[i], -M) : -2.0f;
            unsigned m = __ballot_sync(0xffffffffu, y > -1.0f);
            if (m) {
                int base = 0;
                if (lane == 0) base = atomicAdd(&s_count2, __popc(m));
                base = __shfl_sync(0xffffffffu, base, 0);
                if (y > -1.0f) {
                    int id = base + __popc(m & ((1u << lane) - 1u));
                    if (id < CAP2) candY[id] = y;
                }
            }
        }
    }
    __syncthreads();
    const int  count2 = s_count2;
    const bool fit2 = fit && (count2 <= CAP2);

    // ---- Newton on f(tau) = sum max(Y-tau,0)^2 = 1, root in [-1,0) ----
    // f convex decreasing => monotone convergence from tau = -1.
    float tau;
    if (fit) {
        const float* buf = fit2 ? candY : cand;
        const int    len = fit2 ? count2 : count;
        const bool   isY = fit2;
        if (wid == 0) {
            float tl = -1.0f;
            #pragma unroll 1
            for (int it = 0; it < 20; ++it) {
                float s1 = 0.f, s2 = 0.f;
                for (int i = lane; i < len; i += 32) {
                    float y = isY ? buf[i] : fmaf(0.5f, buf[i], -M);
                    float t = y - tl;
                    if (t > 0.f) { s1 += t; s2 = fmaf(t, t, s2); }
                }
                s1 = warpSum(s1); s2 = warpSum(s2);
                float corr = (s2 - 1.0f) / (2.0f * fmaxf(s1, 1e-30f));
                tl += corr;
                if (fabsf(corr) < 1e-8f) break;
            }
            if (lane == 0) s_tau = tl;
        }
        __syncthreads();
        tau = s_tau;
    } else {
        // Rare fallback: block-wide Newton over the full row (L2 reads).
        tau = -1.0f;
        for (int it = 0; it < 24; ++it) {
            float s1 = 0.f, s2 = 0.f;
            for (int i = tid; i < d; i += bd) {
                float t = fmaf(0.5f, in_row[i], -M) - tau;
                if (t > 0.f) { s1 += t; s2 = fmaf(t, t, s2); }
            }
            s1 = warpSum(s1); s2 = warpSum(s2);
            if (lane == 0) { shA[wid] = s1; shB[wid] = s2; }
            __syncthreads();
            if (tid < 32) {
                float a = (tid < nw) ? shA[tid] : 0.f;
                float b = (tid < nw) ? shB[tid] : 0.f;
                a = warpSum(a); b = warpSum(b);
                if (tid == 0) { s_red0 = a; s_red1 = b; }
            }
            __syncthreads();
            tau += (s_red1 - 1.0f) / (2.0f * fmaxf(s_red0, 1e-30f));
            __syncthreads();
        }
    }

    // ---- Epilogue: loss = (1 - sum t^3)*4/3 + 2*sum t^2*Y + 2*M*sum t^2 - x[tg] ----
    float t3 = 0.f, py = 0.f, p2 = 0.f;
    if (fit) {
        const float* buf = fit2 ? candY : cand;
        const int    len = fit2 ? count2 : count;
        const bool   isY = fit2;
        for (int i = tid; i < len; i += bd) {
            float y = isY ? buf[i] : fmaf(0.5f, buf[i], -M);
            float t = y - tau;
            if (t > 0.f) { float p = t * t; t3 = fmaf(p, t, t3); py = fmaf(p, y, py); p2 += p; }
        }
    } else {
        for (int i = tid; i < d; i += bd) {
            float y = fmaf(0.5f, in_row[i], -M);
            float t = y - tau;
            if (t > 0.f) { float p = t * t; t3 = fmaf(p, t, t3); py = fmaf(p, y, py); p2 += p; }
        }
    }
    t3 = warpSum(t3); py = warpSum(py); p2 = warpSum(p2);
    if (lane == 0) { shA[wid] = t3; shB[wid] = py; shC[wid] = p2; }
    __syncthreads();
    if (tid < 32) {
        float a = (tid < nw) ? shA[tid] : 0.f;
        float b = (tid < nw) ? shB[tid] : 0.f;
        float c = (tid < nw) ? shC[tid] : 0.f;
        a = warpSum(a); b = warpSum(b); c = warpSum(c);
        if (tid == 0) {
            float omega = (1.0f - a) * (4.0f / 3.0f);
            g_row_loss[blockIdx.x] = omega + 2.0f * b + 2.0f * M * c - s_xt;
        }
    }
    __syncthreads();

    // ---- Deterministic in-kernel mean: last block to finish reduces ----
    if (tid == 0) {
        __threadfence();
        unsigned prev = atomicAdd(&g_done, 1u);
        s_last = (prev == (unsigned)(n - 1));
    }
    __syncthreads();
    if (s_last) {
        float a = 0.f;
        for (int i = tid; i < n; i += bd) a += g_row_loss[i];  // fixed order
        a = warpSum(a);
        if (lane == 0) shA[wid] = a;
        __syncthreads();
        if (tid < 32) {
            float v = (tid < nw) ? shA[tid] : 0.f;
            v = warpSum(v);
            if (tid == 0) { out[0] = v / (float)n; g_done = 0u; }
        }
    }
}

extern "C" void kernel_launch(void* const* d_in, const int* in_sizes, int n_in,
                              void* d_out, int out_size) {
    const int i_in = (in_sizes[0] >= in_sizes[1]) ? 0 : 1;
    const int i_tg = 1 - i_in;
    const float* input  = (const float*)d_in[i_in];
    const void*  target = d_in[i_tg];
    const int n = in_sizes[i_tg];
    const int d = in_sizes[i_in] / n;

    entmax15_loss_kernel<<<n, 512>>>(input, target, n, d, (float*)d_out);
}